// round 12
// baseline (speedup 1.0000x reference)
#include <cuda_runtime.h>
#include <cuda_bf16.h>
#include <math.h>
#include <stdint.h>

// ---------------------------------------------------------------------------
// GCN 2-layer: out = log_softmax( A relu( (A x) W1 + b1 ) W2 + b2 )
//   bf16 datapath: x,W1,W2 converted once; gathers + GEMMs in bf16; fp32 accum.
//   layer1: CSR gather-aggregate x (bf16, dim128) -> bf16 MMA GEMM -> 256 (+bias,relu)
//   layer2: bf16 MMA GEMM 256->64 -> CSR gather-aggregate + bias + log_softmax
//   Edge weights are NOT materialized: recomputed as dis[d]*dis[s] in gathers
//   (halves k_place's random-sector writes; g_dis is L2-resident).
//
// RULE (learned R0-R7): __device__ global buffers are NEVER passed as host-side
// kernel arguments (host sees the host shadow; GB300 ATS silently reads zeros).
// ---------------------------------------------------------------------------

#define N_NODES 50000
#define N_EDGES 800000
#define IN_DIM 128
#define HID_DIM 256
#define OUT_DIM 64

__device__ int   g_count[N_NODES];
__device__ int   g_off[N_NODES];
__device__ int   g_cur[N_NODES];
__device__ int   g_cursor;
__device__ int   g_esrc[N_EDGES];
__device__ float g_dis[N_NODES];
__device__ __nv_bfloat16 g_xb[(size_t)N_NODES * IN_DIM];
__device__ __nv_bfloat16 g_w1b[(size_t)HID_DIM * IN_DIM];   // [n][k] transposed
__device__ __nv_bfloat16 g_w2b[(size_t)OUT_DIM * HID_DIM];  // [n][k] transposed
__device__ __nv_bfloat16 g_aggxb[(size_t)N_NODES * IN_DIM];
__device__ __nv_bfloat16 g_h1b[(size_t)N_NODES * HID_DIM];
__device__ __nv_bfloat16 g_t2b[(size_t)N_NODES * OUT_DIM];

// ---------------- prep: zero counters + cvt x,W1,W2 to bf16 ----------------
__global__ __launch_bounds__(256) void k_prep(const float* __restrict__ x,
                                              const float* __restrict__ W1,
                                              const float* __restrict__ W2) {
    int t = blockIdx.x * blockDim.x + threadIdx.x;
    if (t < (N_NODES * IN_DIM) / 4) {
        float4 v = reinterpret_cast<const float4*>(x)[t];
        __nv_bfloat162 p0 = __floats2bfloat162_rn(v.x, v.y);
        __nv_bfloat162 p1 = __floats2bfloat162_rn(v.z, v.w);
        uint2 u;
        u.x = *reinterpret_cast<uint32_t*>(&p0);
        u.y = *reinterpret_cast<uint32_t*>(&p1);
        reinterpret_cast<uint2*>(g_xb)[t] = u;
    }
    if (t < N_NODES) g_count[t] = 0;
    if (t < IN_DIM * HID_DIM) {        // W1[k][n] -> g_w1b[n][k]
        int k = t / HID_DIM, n = t % HID_DIM;
        g_w1b[(size_t)n * IN_DIM + k] = __float2bfloat16_rn(W1[t]);
    }
    if (t < HID_DIM * OUT_DIM) {       // W2[k][n] -> g_w2b[n][k]
        int k = t / OUT_DIM, n = t % OUT_DIM;
        g_w2b[(size_t)n * HID_DIM + k] = __float2bfloat16_rn(W2[t]);
    }
    if (t == 0) g_cursor = 0;
}

// ---------------- CSR build ----------------
__global__ void k_hist(const int* __restrict__ dst, int e) {
    int i = blockIdx.x * blockDim.x + threadIdx.x;
    if (i < e) atomicAdd(&g_count[dst[i]], 1);
}

// fused per-chunk scan + atomic base grab (segments need not be node-ordered:
// lengths come from g_count, so any disjoint contiguous assignment is valid)
__global__ __launch_bounds__(1024) void k_offsets(int n) {
    __shared__ int sh[1024];
    __shared__ int sbase;
    int i = blockIdx.x * 1024 + threadIdx.x;
    int c = (i < n) ? g_count[i] : 0;
    sh[threadIdx.x] = c;
    __syncthreads();
    for (int o = 1; o < 1024; o <<= 1) {
        int t = 0;
        if (threadIdx.x >= o) t = sh[threadIdx.x - o];
        __syncthreads();
        sh[threadIdx.x] += t;
        __syncthreads();
    }
    if (threadIdx.x == 1023) sbase = atomicAdd(&g_cursor, sh[1023]);
    __syncthreads();
    if (i < n) {
        int off = sbase + sh[threadIdx.x] - c;   // exclusive within chunk
        g_off[i] = off;
        g_cur[i] = off;
        g_dis[i] = rsqrtf((float)(c + 1));       // +1 self-loop
    }
}

// place: ONE random 4B store per edge (weights recomputed later on the fly)
__global__ void k_place(const int* __restrict__ src, const int* __restrict__ dst, int e) {
    int i = blockIdx.x * blockDim.x + threadIdx.x;
    if (i >= e) return;
    int s = src[i], d = dst[i];
    int pos = atomicAdd(&g_cur[d], 1);
    g_esrc[pos] = s;
}

// ------- layer-1 aggregation: gather bf16, warp per node, dim 128 ----------
// 2-edge unroll for MLP; weight = dis_d * g_dis[s] (L2-resident table).
__global__ __launch_bounds__(256) void k_agg128() {
    int gid = blockIdx.x * blockDim.x + threadIdx.x;
    int node = gid >> 5;
    int lane = gid & 31;
    if (node >= N_NODES) return;
    const uint2* xv = reinterpret_cast<const uint2*>(g_xb);  // 32 uint2 per row
    float dis_d = g_dis[node];
    float s2 = dis_d * dis_d;
    uint2 u = xv[(size_t)node * 32 + lane];                  // self-loop
    float2 lo = __bfloat1622float2(*reinterpret_cast<__nv_bfloat162*>(&u.x));
    float2 hi = __bfloat1622float2(*reinterpret_cast<__nv_bfloat162*>(&u.y));
    float a0 = lo.x * s2, a1 = lo.y * s2, a2 = hi.x * s2, a3 = hi.y * s2;
    int p0 = g_off[node];
    int p1 = p0 + g_count[node];
    int p = p0;
    for (; p + 2 <= p1; p += 2) {
        int s0 = g_esrc[p];
        int s1 = g_esrc[p + 1];
        float w0 = dis_d * g_dis[s0];
        float w1 = dis_d * g_dis[s1];
        uint2 v0 = xv[(size_t)s0 * 32 + lane];
        uint2 v1 = xv[(size_t)s1 * 32 + lane];
        float2 v0l = __bfloat1622float2(*reinterpret_cast<__nv_bfloat162*>(&v0.x));
        float2 v0h = __bfloat1622float2(*reinterpret_cast<__nv_bfloat162*>(&v0.y));
        float2 v1l = __bfloat1622float2(*reinterpret_cast<__nv_bfloat162*>(&v1.x));
        float2 v1h = __bfloat1622float2(*reinterpret_cast<__nv_bfloat162*>(&v1.y));
        a0 = fmaf(w0, v0l.x, a0); a1 = fmaf(w0, v0l.y, a1);
        a2 = fmaf(w0, v0h.x, a2); a3 = fmaf(w0, v0h.y, a3);
        a0 = fmaf(w1, v1l.x, a0); a1 = fmaf(w1, v1l.y, a1);
        a2 = fmaf(w1, v1h.x, a2); a3 = fmaf(w1, v1h.y, a3);
    }
    if (p < p1) {
        int s0 = g_esrc[p];
        float w0 = dis_d * g_dis[s0];
        uint2 v0 = xv[(size_t)s0 * 32 + lane];
        float2 v0l = __bfloat1622float2(*reinterpret_cast<__nv_bfloat162*>(&v0.x));
        float2 v0h = __bfloat1622float2(*reinterpret_cast<__nv_bfloat162*>(&v0.y));
        a0 = fmaf(w0, v0l.x, a0); a1 = fmaf(w0, v0l.y, a1);
        a2 = fmaf(w0, v0h.x, a2); a3 = fmaf(w0, v0h.y, a3);
    }
    __nv_bfloat162 r0 = __floats2bfloat162_rn(a0, a1);
    __nv_bfloat162 r1 = __floats2bfloat162_rn(a2, a3);
    uint2 w;
    w.x = *reinterpret_cast<uint32_t*>(&r0);
    w.y = *reinterpret_cast<uint32_t*>(&r1);
    reinterpret_cast<uint2*>(g_aggxb)[(size_t)node * 32 + lane] = w;
}

// ---------------- bf16 tensor-core GEMM ------------------------------------
__device__ __forceinline__ void mma_bf16(float c[4], const uint32_t a[4], const uint32_t b[2]) {
    asm volatile(
        "mma.sync.aligned.m16n8k16.row.col.f32.bf16.bf16.f32 "
        "{%0,%1,%2,%3}, {%4,%5,%6,%7}, {%8,%9}, {%0,%1,%2,%3};"
        : "+f"(c[0]), "+f"(c[1]), "+f"(c[2]), "+f"(c[3])
        : "r"(a[0]), "r"(a[1]), "r"(a[2]), "r"(a[3]), "r"(b[0]), "r"(b[1]));
}

template <int LAYER, int N_COLS, int K_DIM, int BN, bool RELU, bool ADD_BIAS>
__global__ __launch_bounds__(64 * (BN / 32)) void k_gemm_bf16(
        const float* __restrict__ bias, int M) {
    const __nv_bfloat16* __restrict__ A  = (LAYER == 1) ? g_aggxb : g_h1b;
    const __nv_bfloat16* __restrict__ Wb = (LAYER == 1) ? g_w1b   : g_w2b;
    __nv_bfloat16* __restrict__ C        = (LAYER == 1) ? g_h1b   : g_t2b;

    constexpr int BM = 128, BK = 32;
    constexpr int THREADS = 64 * (BN / 32);
    constexpr int AS = 20;   // uint32 stride: 16 data + 4 pad (conflict-free)

    __shared__ uint32_t As32[BM * AS];
    __shared__ uint32_t Bs32[BN * AS];

    int tid = threadIdx.x;
    int warp = tid >> 5, lane = tid & 31;
    int g = lane >> 2, t = lane & 3;
    int wm = warp & 1;
    int wn = warp >> 1;
    int row0 = blockIdx.x * BM;
    int col0 = blockIdx.y * BN;

    float c[4][4][4];
    #pragma unroll
    for (int i = 0; i < 4; i++)
        #pragma unroll
        for (int j = 0; j < 4; j++)
            #pragma unroll
            for (int r = 0; r < 4; r++) c[i][j][r] = 0.0f;

    for (int k0 = 0; k0 < K_DIM; k0 += BK) {
        constexpr int ALOADS = (BM * 4) / THREADS;
        #pragma unroll
        for (int i = 0; i < ALOADS; i++) {
            int f = tid + i * THREADS;
            int row = f >> 2, q = f & 3;
            int gr = row0 + row;
            uint4 u = make_uint4(0, 0, 0, 0);
            if (gr < M) u = *reinterpret_cast<const uint4*>(A + (size_t)gr * K_DIM + k0 + q * 8);
            uint32_t* p = &As32[row * AS + q * 4];
            p[0] = u.x; p[1] = u.y; p[2] = u.z; p[3] = u.w;
        }
        constexpr int BLOADS = (BN * 4) / THREADS;
        #pragma unroll
        for (int i = 0; i < BLOADS; i++) {
            int f = tid + i * THREADS;
            int row = f >> 2, q = f & 3;
            uint4 u = *reinterpret_cast<const uint4*>(Wb + (size_t)(col0 + row) * K_DIM + k0 + q * 8);
            uint32_t* p = &Bs32[row * AS + q * 4];
            p[0] = u.x; p[1] = u.y; p[2] = u.z; p[3] = u.w;
        }
        __syncthreads();

        #pragma unroll
        for (int ch = 0; ch < 2; ch++) {
            int kb2 = ch * 8;
            uint32_t a[4][4], b[4][2];
            #pragma unroll
            for (int mt = 0; mt < 4; mt++) {
                int r = wm * 64 + mt * 16 + g;
                a[mt][0] = As32[r * AS + kb2 + t];
                a[mt][1] = As32[(r + 8) * AS + kb2 + t];
                a[mt][2] = As32[r * AS + kb2 + 4 + t];
                a[mt][3] = As32[(r + 8) * AS + kb2 + 4 + t];
            }
            #pragma unroll
            for (int nt = 0; nt < 4; nt++) {
                int cc = wn * 32 + nt * 8 + g;
                b[nt][0] = Bs32[cc * AS + kb2 + t];
                b[nt][1] = Bs32[cc * AS + kb2 + 4 + t];
            }
            #pragma unroll
            for (int mt = 0; mt < 4; mt++)
                #pragma unroll
                for (int nt = 0; nt < 4; nt++)
                    mma_bf16(c[mt][nt], a[mt], b[nt]);
        }
        __syncthreads();
    }

    #pragma unroll
    for (int mt = 0; mt < 4; mt++) {
        int r0 = row0 + wm * 64 + mt * 16 + g;
        #pragma unroll
        for (int nt = 0; nt < 4; nt++) {
            int col = col0 + wn * 32 + nt * 8 + 2 * t;
            float bb0 = 0.f, bb1 = 0.f;
            if (ADD_BIAS) { bb0 = bias[col]; bb1 = bias[col + 1]; }
            if (r0 < M) {
                float v0 = c[mt][nt][0] + bb0;
                float v1 = c[mt][nt][1] + bb1;
                if (RELU) { v0 = fmaxf(v0, 0.f); v1 = fmaxf(v1, 0.f); }
                *reinterpret_cast<__nv_bfloat162*>(C + (size_t)r0 * N_COLS + col) =
                    __floats2bfloat162_rn(v0, v1);
            }
            if (r0 + 8 < M) {
                float v0 = c[mt][nt][2] + bb0;
                float v1 = c[mt][nt][3] + bb1;
                if (RELU) { v0 = fmaxf(v0, 0.f); v1 = fmaxf(v1, 0.f); }
                *reinterpret_cast<__nv_bfloat162*>(C + (size_t)(r0 + 8) * N_COLS + col) =
                    __floats2bfloat162_rn(v0, v1);
            }
        }
    }
}

// ------- layer-2 aggregation (bf16, dim 64) + bias + log_softmax -----------
__global__ __launch_bounds__(256) void k_agg64_softmax(float* __restrict__ out,
                                                       const float* __restrict__ b2,
                                                       const float* __restrict__ x,
                                                       const float* __restrict__ W1) {
    int gid = blockIdx.x * blockDim.x + threadIdx.x;
    int node = gid >> 5;
    int lane = gid & 31;
    if (node >= N_NODES) return;
    const __nv_bfloat162* tv = reinterpret_cast<const __nv_bfloat162*>(g_t2b);  // 32 per row
    float dis_d = g_dis[node];
    float s2 = dis_d * dis_d;
    float2 acc = __bfloat1622float2(tv[(size_t)node * 32 + lane]);  // self-loop
    acc.x *= s2; acc.y *= s2;
    int p0 = g_off[node];
    int p1 = p0 + g_count[node];
    int p = p0;
    for (; p + 2 <= p1; p += 2) {
        int s0 = g_esrc[p];
        int s1 = g_esrc[p + 1];
        float w0 = dis_d * g_dis[s0];
        float w1 = dis_d * g_dis[s1];
        float2 v0 = __bfloat1622float2(tv[(size_t)s0 * 32 + lane]);
        float2 v1 = __bfloat1622float2(tv[(size_t)s1 * 32 + lane]);
        acc.x = fmaf(w0, v0.x, acc.x); acc.y = fmaf(w0, v0.y, acc.y);
        acc.x = fmaf(w1, v1.x, acc.x); acc.y = fmaf(w1, v1.y, acc.y);
    }
    if (p < p1) {
        int s0 = g_esrc[p];
        float w0 = dis_d * g_dis[s0];
        float2 v0 = __bfloat1622float2(tv[(size_t)s0 * 32 + lane]);
        acc.x = fmaf(w0, v0.x, acc.x); acc.y = fmaf(w0, v0.y, acc.y);
    }

    // --- diagnostic canaries (0.0 contribution when all stages are live) ---
    float canary = 0.0f;
    if (x[5] == 0.0f && x[777] == 0.0f)                       canary += 0.64f;
    if (W1[3] == 0.0f && W1[1000] == 0.0f)                    canary += 0.32f;
    if (__bfloat162float(g_aggxb[12345]) == 0.0f &&
        __bfloat162float(g_aggxb[4000001]) == 0.0f)           canary += 0.16f;
    if (__bfloat162float(g_h1b[54321]) == 0.0f &&
        __bfloat162float(g_h1b[9000001]) == 0.0f)             canary += 0.08f;
    if (g_dis[7] == 0.0f)                                     canary += 0.04f;
    if (g_cursor != N_EDGES)                                  canary += 0.02f;

    float2 bb = reinterpret_cast<const float2*>(b2)[lane];
    float vx = acc.x + bb.x + canary;
    float vy = acc.y + bb.y - canary;

    float m = fmaxf(vx, vy);
    #pragma unroll
    for (int o = 16; o > 0; o >>= 1) m = fmaxf(m, __shfl_xor_sync(0xFFFFFFFF, m, o));
    float s = expf(vx - m) + expf(vy - m);
    #pragma unroll
    for (int o = 16; o > 0; o >>= 1) s += __shfl_xor_sync(0xFFFFFFFF, s, o);
    float lse = m + logf(s);

    float2 r;
    r.x = vx - lse;
    r.y = vy - lse;
    reinterpret_cast<float2*>(out + (size_t)node * OUT_DIM)[lane] = r;
}

// ---------------------------------------------------------------------------
extern "C" void kernel_launch(void* const* d_in, const int* in_sizes, int n_in,
                              void* d_out, int out_size) {
    const float* x  = nullptr;   // 6400000
    const int*   ei = nullptr;   // 1600000
    const float* W1 = nullptr;   // 32768
    const float* b1 = nullptr;   // 256
    const float* W2 = nullptr;   // 16384
    const float* b2 = nullptr;   // 64
    for (int i = 0; i < n_in; i++) {
        switch (in_sizes[i]) {
            case N_NODES * IN_DIM:   x  = (const float*)d_in[i]; break;
            case 2 * N_EDGES:        ei = (const int*)d_in[i];   break;
            case IN_DIM * HID_DIM:   W1 = (const float*)d_in[i]; break;
            case HID_DIM:            b1 = (const float*)d_in[i]; break;
            case HID_DIM * OUT_DIM:  W2 = (const float*)d_in[i]; break;
            case OUT_DIM:            b2 = (const float*)d_in[i]; break;
            default: break;
        }
    }
    float* out = (float*)d_out;

    const int N = N_NODES;
    const int E = N_EDGES;
    const int* src = ei;
    const int* dst = ei + E;

    const int T = 256;

    k_prep<<<(N * IN_DIM / 4 + T - 1) / T, T>>>(x, W1, W2);
    k_hist<<<(E + T - 1) / T, T>>>(dst, E);
    k_offsets<<<(N + 1023) / 1024, 1024>>>(N);
    k_place<<<(E + T - 1) / T, T>>>(src, dst, E);

    k_agg128<<<(N * 32 + T - 1) / T, T>>>();
    {
        dim3 g((N + 127) / 128, HID_DIM / 128);   // (391, 2)
        k_gemm_bf16<1, HID_DIM, IN_DIM, 128, true, true><<<g, 256>>>(b1, N);
    }
    {
        dim3 g((N + 127) / 128, 1);               // (391, 1)
        k_gemm_bf16<2, OUT_DIM, HID_DIM, 64, false, false><<<g, 128>>>(nullptr, N);
    }
    k_agg64_softmax<<<(N * 32 + T - 1) / T, T>>>(out, b2, x, W1);
}

// round 15
// speedup vs baseline: 1.0173x; 1.0173x over previous
#include <cuda_runtime.h>
#include <cuda_bf16.h>
#include <math.h>
#include <stdint.h>

// ---------------------------------------------------------------------------
// GCN 2-layer: out = log_softmax( A relu( (A x) W1 + b1 ) W2 + b2 )
//   bf16 datapath; fp32 accum. CSR gather aggregation.
//   Streaming conversions fused into latency-bound CSR kernels (issue ~4%).
//   R15 FIX: x->bf16 conversion in k_place_x now covers ALL 1.6M float4s
//   (R13/R14 covered only half -> half of g_xb stayed zero -> rel_err 1e-2).
//   Self-cleaning state: k_offsets zeroes g_count after reading it, so every
//   run (correctness / capture / replay) starts from identical state.
//
// RULE (learned R0-R7): __device__ global buffers are NEVER passed as host-side
// kernel arguments (host sees the host shadow; GB300 ATS silently reads zeros).
// ---------------------------------------------------------------------------

#define N_NODES 50000
#define N_EDGES 800000
#define IN_DIM 128
#define HID_DIM 256
#define OUT_DIM 64

__device__ int   g_count[N_NODES];    // zero at load; re-zeroed by k_offsets each run
__device__ int   g_off[N_NODES];
__device__ int   g_cur[N_NODES];      // after k_place: segment END per node
__device__ int   g_cursor;
__device__ int   g_esrc[N_EDGES];
__device__ float g_dis[N_NODES];
__device__ __nv_bfloat16 g_xb[(size_t)N_NODES * IN_DIM];
__device__ __nv_bfloat16 g_w1b[(size_t)HID_DIM * IN_DIM];   // [n][k] transposed
__device__ __nv_bfloat16 g_w2b[(size_t)OUT_DIM * HID_DIM];  // [n][k] transposed
__device__ __nv_bfloat16 g_aggxb[(size_t)N_NODES * IN_DIM];
__device__ __nv_bfloat16 g_h1b[(size_t)N_NODES * HID_DIM];
__device__ __nv_bfloat16 g_t2b[(size_t)N_NODES * OUT_DIM];

// ------- hist (atomic-latency-bound) + W conversions (streaming, fused) ----
__global__ void k_hist_w(const int* __restrict__ dst,
                         const float* __restrict__ W1,
                         const float* __restrict__ W2, int e) {
    int i = blockIdx.x * blockDim.x + threadIdx.x;
    if (i < e) atomicAdd(&g_count[dst[i]], 1);
    if (i < IN_DIM * HID_DIM) {        // W1[k][n] -> g_w1b[n][k]
        int k = i / HID_DIM, n = i % HID_DIM;
        g_w1b[(size_t)n * IN_DIM + k] = __float2bfloat16_rn(W1[i]);
    }
    if (i < HID_DIM * OUT_DIM) {       // W2[k][n] -> g_w2b[n][k]
        int k = i / OUT_DIM, n = i % OUT_DIM;
        g_w2b[(size_t)n * HID_DIM + k] = __float2bfloat16_rn(W2[i]);
    }
    if (i == 0) g_cursor = 0;
}

// fused per-chunk scan + atomic base grab; SELF-CLEANS g_count for next run.
__global__ __launch_bounds__(1024) void k_offsets(int n) {
    __shared__ int sh[1024];
    __shared__ int sbase;
    int i = blockIdx.x * 1024 + threadIdx.x;
    int c = (i < n) ? g_count[i] : 0;
    if (i < n) g_count[i] = 0;         // self-clean (each i touched by one thread)
    sh[threadIdx.x] = c;
    __syncthreads();
    for (int o = 1; o < 1024; o <<= 1) {
        int t = 0;
        if (threadIdx.x >= o) t = sh[threadIdx.x - o];
        __syncthreads();
        sh[threadIdx.x] += t;
        __syncthreads();
    }
    if (threadIdx.x == 1023) sbase = atomicAdd(&g_cursor, sh[1023]);
    __syncthreads();
    if (i < n) {
        int off = sbase + sh[threadIdx.x] - c;   // exclusive within chunk
        g_off[i] = off;
        g_cur[i] = off;
        g_dis[i] = rsqrtf((float)(c + 1));       // +1 self-loop
    }
}

// ------- place (atomic-latency-bound) + x->bf16 conversion (fused) ---------
// After this kernel, g_cur[d] == segment end for node d.
// Conversion strides by total thread count to cover ALL 1.6M float4s (R15 fix).
__global__ void k_place_x(const int* __restrict__ src, const int* __restrict__ dst,
                          const float* __restrict__ x, int e) {
    int i = blockIdx.x * blockDim.x + threadIdx.x;
    if (i < e) {
        int s = src[i], d = dst[i];
        int pos = atomicAdd(&g_cur[d], 1);
        g_esrc[pos] = s;
    }
    int nthreads = gridDim.x * blockDim.x;
    for (int j = i; j < (N_NODES * IN_DIM) / 4; j += nthreads) {
        float4 v = reinterpret_cast<const float4*>(x)[j];
        __nv_bfloat162 p0 = __floats2bfloat162_rn(v.x, v.y);
        __nv_bfloat162 p1 = __floats2bfloat162_rn(v.z, v.w);
        uint2 u;
        u.x = *reinterpret_cast<uint32_t*>(&p0);
        u.y = *reinterpret_cast<uint32_t*>(&p1);
        reinterpret_cast<uint2*>(g_xb)[j] = u;
    }
}

// ------- layer-1 aggregation: gather bf16, warp per node, dim 128 ----------
__global__ __launch_bounds__(256) void k_agg128() {
    int gid = blockIdx.x * blockDim.x + threadIdx.x;
    int node = gid >> 5;
    int lane = gid & 31;
    if (node >= N_NODES) return;
    const uint2* xv = reinterpret_cast<const uint2*>(g_xb);  // 32 uint2 per row
    float dis_d = g_dis[node];
    float s2 = dis_d * dis_d;
    uint2 u = xv[(size_t)node * 32 + lane];                  // self-loop
    float2 lo = __bfloat1622float2(*reinterpret_cast<__nv_bfloat162*>(&u.x));
    float2 hi = __bfloat1622float2(*reinterpret_cast<__nv_bfloat162*>(&u.y));
    float a0 = lo.x * s2, a1 = lo.y * s2, a2 = hi.x * s2, a3 = hi.y * s2;
    int p = g_off[node];
    int p1 = g_cur[node];              // segment end (off + count)
    for (; p + 2 <= p1; p += 2) {
        int s0 = g_esrc[p];
        int s1 = g_esrc[p + 1];
        float w0 = dis_d * g_dis[s0];
        float w1 = dis_d * g_dis[s1];
        uint2 v0 = xv[(size_t)s0 * 32 + lane];
        uint2 v1 = xv[(size_t)s1 * 32 + lane];
        float2 v0l = __bfloat1622float2(*reinterpret_cast<__nv_bfloat162*>(&v0.x));
        float2 v0h = __bfloat1622float2(*reinterpret_cast<__nv_bfloat162*>(&v0.y));
        float2 v1l = __bfloat1622float2(*reinterpret_cast<__nv_bfloat162*>(&v1.x));
        float2 v1h = __bfloat1622float2(*reinterpret_cast<__nv_bfloat162*>(&v1.y));
        a0 = fmaf(w0, v0l.x, a0); a1 = fmaf(w0, v0l.y, a1);
        a2 = fmaf(w0, v0h.x, a2); a3 = fmaf(w0, v0h.y, a3);
        a0 = fmaf(w1, v1l.x, a0); a1 = fmaf(w1, v1l.y, a1);
        a2 = fmaf(w1, v1h.x, a2); a3 = fmaf(w1, v1h.y, a3);
    }
    if (p < p1) {
        int s0 = g_esrc[p];
        float w0 = dis_d * g_dis[s0];
        uint2 v0 = xv[(size_t)s0 * 32 + lane];
        float2 v0l = __bfloat1622float2(*reinterpret_cast<__nv_bfloat162*>(&v0.x));
        float2 v0h = __bfloat1622float2(*reinterpret_cast<__nv_bfloat162*>(&v0.y));
        a0 = fmaf(w0, v0l.x, a0); a1 = fmaf(w0, v0l.y, a1);
        a2 = fmaf(w0, v0h.x, a2); a3 = fmaf(w0, v0h.y, a3);
    }
    __nv_bfloat162 r0 = __floats2bfloat162_rn(a0, a1);
    __nv_bfloat162 r1 = __floats2bfloat162_rn(a2, a3);
    uint2 w;
    w.x = *reinterpret_cast<uint32_t*>(&r0);
    w.y = *reinterpret_cast<uint32_t*>(&r1);
    reinterpret_cast<uint2*>(g_aggxb)[(size_t)node * 32 + lane] = w;
}

// ---------------- bf16 tensor-core GEMM ------------------------------------
__device__ __forceinline__ void mma_bf16(float c[4], const uint32_t a[4], const uint32_t b[2]) {
    asm volatile(
        "mma.sync.aligned.m16n8k16.row.col.f32.bf16.bf16.f32 "
        "{%0,%1,%2,%3}, {%4,%5,%6,%7}, {%8,%9}, {%0,%1,%2,%3};"
        : "+f"(c[0]), "+f"(c[1]), "+f"(c[2]), "+f"(c[3])
        : "r"(a[0]), "r"(a[1]), "r"(a[2]), "r"(a[3]), "r"(b[0]), "r"(b[1]));
}

template <int LAYER, int N_COLS, int K_DIM, int BN, bool RELU, bool ADD_BIAS>
__global__ __launch_bounds__(64 * (BN / 32)) void k_gemm_bf16(
        const float* __restrict__ bias, int M) {
    const __nv_bfloat16* __restrict__ A  = (LAYER == 1) ? g_aggxb : g_h1b;
    const __nv_bfloat16* __restrict__ Wb = (LAYER == 1) ? g_w1b   : g_w2b;
    __nv_bfloat16* __restrict__ C        = (LAYER == 1) ? g_h1b   : g_t2b;

    constexpr int BM = 128, BK = 32;
    constexpr int THREADS = 64 * (BN / 32);
    constexpr int AS = 20;   // uint32 stride: 16 data + 4 pad (conflict-free)

    __shared__ uint32_t As32[BM * AS];
    __shared__ uint32_t Bs32[BN * AS];

    int tid = threadIdx.x;
    int warp = tid >> 5, lane = tid & 31;
    int g = lane >> 2, t = lane & 3;
    int wm = warp & 1;
    int wn = warp >> 1;
    int row0 = blockIdx.x * BM;
    int col0 = blockIdx.y * BN;

    float c[4][4][4];
    #pragma unroll
    for (int i = 0; i < 4; i++)
        #pragma unroll
        for (int j = 0; j < 4; j++)
            #pragma unroll
            for (int r = 0; r < 4; r++) c[i][j][r] = 0.0f;

    for (int k0 = 0; k0 < K_DIM; k0 += BK) {
        constexpr int ALOADS = (BM * 4) / THREADS;
        #pragma unroll
        for (int i = 0; i < ALOADS; i++) {
            int f = tid + i * THREADS;
            int row = f >> 2, q = f & 3;
            int gr = row0 + row;
            uint4 u = make_uint4(0, 0, 0, 0);
            if (gr < M) u = *reinterpret_cast<const uint4*>(A + (size_t)gr * K_DIM + k0 + q * 8);
            uint32_t* p = &As32[row * AS + q * 4];
            p[0] = u.x; p[1] = u.y; p[2] = u.z; p[3] = u.w;
        }
        constexpr int BLOADS = (BN * 4) / THREADS;
        #pragma unroll
        for (int i = 0; i < BLOADS; i++) {
            int f = tid + i * THREADS;
            int row = f >> 2, q = f & 3;
            uint4 u = *reinterpret_cast<const uint4*>(Wb + (size_t)(col0 + row) * K_DIM + k0 + q * 8);
            uint32_t* p = &Bs32[row * AS + q * 4];
            p[0] = u.x; p[1] = u.y; p[2] = u.z; p[3] = u.w;
        }
        __syncthreads();

        #pragma unroll
        for (int ch = 0; ch < 2; ch++) {
            int kb2 = ch * 8;
            uint32_t a[4][4], b[4][2];
            #pragma unroll
            for (int mt = 0; mt < 4; mt++) {
                int r = wm * 64 + mt * 16 + g;
                a[mt][0] = As32[r * AS + kb2 + t];
                a[mt][1] = As32[(r + 8) * AS + kb2 + t];
                a[mt][2] = As32[r * AS + kb2 + 4 + t];
                a[mt][3] = As32[(r + 8) * AS + kb2 + 4 + t];
            }
            #pragma unroll
            for (int nt = 0; nt < 4; nt++) {
                int cc = wn * 32 + nt * 8 + g;
                b[nt][0] = Bs32[cc * AS + kb2 + t];
                b[nt][1] = Bs32[cc * AS + kb2 + 4 + t];
            }
            #pragma unroll
            for (int mt = 0; mt < 4; mt++)
                #pragma unroll
                for (int nt = 0; nt < 4; nt++)
                    mma_bf16(c[mt][nt], a[mt], b[nt]);
        }
        __syncthreads();
    }

    #pragma unroll
    for (int mt = 0; mt < 4; mt++) {
        int r0 = row0 + wm * 64 + mt * 16 + g;
        #pragma unroll
        for (int nt = 0; nt < 4; nt++) {
            int col = col0 + wn * 32 + nt * 8 + 2 * t;
            float bb0 = 0.f, bb1 = 0.f;
            if (ADD_BIAS) { bb0 = bias[col]; bb1 = bias[col + 1]; }
            if (r0 < M) {
                float v0 = c[mt][nt][0] + bb0;
                float v1 = c[mt][nt][1] + bb1;
                if (RELU) { v0 = fmaxf(v0, 0.f); v1 = fmaxf(v1, 0.f); }
                *reinterpret_cast<__nv_bfloat162*>(C + (size_t)r0 * N_COLS + col) =
                    __floats2bfloat162_rn(v0, v1);
            }
            if (r0 + 8 < M) {
                float v0 = c[mt][nt][2] + bb0;
                float v1 = c[mt][nt][3] + bb1;
                if (RELU) { v0 = fmaxf(v0, 0.f); v1 = fmaxf(v1, 0.f); }
                *reinterpret_cast<__nv_bfloat162*>(C + (size_t)(r0 + 8) * N_COLS + col) =
                    __floats2bfloat162_rn(v0, v1);
            }
        }
    }
}

// ------- layer-2 aggregation (bf16, dim 64) + bias + log_softmax -----------
__global__ __launch_bounds__(256) void k_agg64_softmax(float* __restrict__ out,
                                                       const float* __restrict__ b2,
                                                       const float* __restrict__ x,
                                                       const float* __restrict__ W1) {
    int gid = blockIdx.x * blockDim.x + threadIdx.x;
    int node = gid >> 5;
    int lane = gid & 31;
    if (node >= N_NODES) return;
    const __nv_bfloat162* tv = reinterpret_cast<const __nv_bfloat162*>(g_t2b);  // 32 per row
    float dis_d = g_dis[node];
    float s2 = dis_d * dis_d;
    float2 acc = __bfloat1622float2(tv[(size_t)node * 32 + lane]);  // self-loop
    acc.x *= s2; acc.y *= s2;
    int p = g_off[node];
    int p1 = g_cur[node];              // segment end
    for (; p + 2 <= p1; p += 2) {
        int s0 = g_esrc[p];
        int s1 = g_esrc[p + 1];
        float w0 = dis_d * g_dis[s0];
        float w1 = dis_d * g_dis[s1];
        float2 v0 = __bfloat1622float2(tv[(size_t)s0 * 32 + lane]);
        float2 v1 = __bfloat1622float2(tv[(size_t)s1 * 32 + lane]);
        acc.x = fmaf(w0, v0.x, acc.x); acc.y = fmaf(w0, v0.y, acc.y);
        acc.x = fmaf(w1, v1.x, acc.x); acc.y = fmaf(w1, v1.y, acc.y);
    }
    if (p < p1) {
        int s0 = g_esrc[p];
        float w0 = dis_d * g_dis[s0];
        float2 v0 = __bfloat1622float2(tv[(size_t)s0 * 32 + lane]);
        acc.x = fmaf(w0, v0.x, acc.x); acc.y = fmaf(w0, v0.y, acc.y);
    }

    // --- diagnostic canaries (0.0 contribution when all stages are live) ---
    float canary = 0.0f;
    if (x[5] == 0.0f && x[777] == 0.0f)                       canary += 0.64f;
    if (W1[3] == 0.0f && W1[1000] == 0.0f)                    canary += 0.32f;
    if (__bfloat162float(g_xb[12345]) == 0.0f &&
        __bfloat162float(g_xb[6399999]) == 0.0f)              canary += 0.16f;
    if (__bfloat162float(g_h1b[54321]) == 0.0f &&
        __bfloat162float(g_h1b[9000001]) == 0.0f)             canary += 0.08f;
    if (g_dis[7] == 0.0f)                                     canary += 0.04f;
    if (g_cursor != N_EDGES)                                  canary += 0.02f;

    float2 bb = reinterpret_cast<const float2*>(b2)[lane];
    float vx = acc.x + bb.x + canary;
    float vy = acc.y + bb.y - canary;

    float m = fmaxf(vx, vy);
    #pragma unroll
    for (int o = 16; o > 0; o >>= 1) m = fmaxf(m, __shfl_xor_sync(0xFFFFFFFF, m, o));
    float s = expf(vx - m) + expf(vy - m);
    #pragma unroll
    for (int o = 16; o > 0; o >>= 1) s += __shfl_xor_sync(0xFFFFFFFF, s, o);
    float lse = m + logf(s);

    float2 r;
    r.x = vx - lse;
    r.y = vy - lse;
    reinterpret_cast<float2*>(out + (size_t)node * OUT_DIM)[lane] = r;
}

// ---------------------------------------------------------------------------
extern "C" void kernel_launch(void* const* d_in, const int* in_sizes, int n_in,
                              void* d_out, int out_size) {
    const float* x  = nullptr;   // 6400000
    const int*   ei = nullptr;   // 1600000
    const float* W1 = nullptr;   // 32768
    const float* b1 = nullptr;   // 256
    const float* W2 = nullptr;   // 16384
    const float* b2 = nullptr;   // 64
    for (int i = 0; i < n_in; i++) {
        switch (in_sizes[i]) {
            case N_NODES * IN_DIM:   x  = (const float*)d_in[i]; break;
            case 2 * N_EDGES:        ei = (const int*)d_in[i];   break;
            case IN_DIM * HID_DIM:   W1 = (const float*)d_in[i]; break;
            case HID_DIM:            b1 = (const float*)d_in[i]; break;
            case HID_DIM * OUT_DIM:  W2 = (const float*)d_in[i]; break;
            case OUT_DIM:            b2 = (const float*)d_in[i]; break;
            default: break;
        }
    }
    float* out = (float*)d_out;

    const int N = N_NODES;
    const int E = N_EDGES;
    const int* src = ei;
    const int* dst = ei + E;

    const int T = 256;

    // CSR build; g_count arrives zeroed (loader on first call, k_offsets after)
    k_hist_w<<<(E + T - 1) / T, T>>>(dst, W1, W2, E);
    k_offsets<<<(N + 1023) / 1024, 1024>>>(N);
    k_place_x<<<(E + T - 1) / T, T>>>(src, dst, x, E);

    // layer 1: bf16 gather-aggregate (dim 128), bf16 GEMM 128->256 (+bias+relu)
    k_agg128<<<(N * 32 + T - 1) / T, T>>>();
    {
        dim3 g((N + 127) / 128, HID_DIM / 128);   // (391, 2)
        k_gemm_bf16<1, HID_DIM, IN_DIM, 128, true, true><<<g, 256>>>(b1, N);
    }
    // layer 2: bf16 GEMM 256->64, then bf16 gather-aggregate + bias + log_softmax
    {
        dim3 g((N + 127) / 128, 1);               // (391, 1)
        k_gemm_bf16<2, OUT_DIM, HID_DIM, 64, false, false><<<g, 128>>>(nullptr, N);
    }
    k_agg64_softmax<<<(N * 32 + T - 1) / T, T>>>(out, b2, x, W1);
}

// round 16
// speedup vs baseline: 1.1330x; 1.1137x over previous
#include <cuda_runtime.h>
#include <cuda_bf16.h>
#include <math.h>
#include <stdint.h>

// ---------------------------------------------------------------------------
// GCN 2-layer: out = log_softmax( A relu( (A x) W1 + b1 ) W2 + b2 )
//   bf16 datapath; fp32 accum. CSR gather aggregation.
//   R16: normalization FACTORED OUT of the edge loops (ncu showed agg128 is
//   issue-bound: alu 41%, fma 27%). Rows are pre-scaled by dis at storage:
//     g_xb[s]  = dis_s * x[s]   (scaled in k_place_x, after k_offsets)
//     g_t2b[s] = dis_s * t2[s]  (scaled in GEMM2 epilogue)
//   so aggregation is an unweighted sum, finished by one *dis_d per lane:
//     aggx[d] = dis_d * ( sum_{s in N(d)} g_xb[s] + g_xb[d] )
//   Self-cleaning state: k_offsets zeroes g_count after reading it.
//
// RULE (learned R0-R7): __device__ global buffers are NEVER passed as host-side
// kernel arguments (host sees the host shadow; GB300 ATS silently reads zeros).
// ---------------------------------------------------------------------------

#define N_NODES 50000
#define N_EDGES 800000
#define IN_DIM 128
#define HID_DIM 256
#define OUT_DIM 64

__device__ int   g_count[N_NODES];    // zero at load; re-zeroed by k_offsets each run
__device__ int   g_off[N_NODES];
__device__ int   g_cur[N_NODES];      // after k_place: segment END per node
__device__ int   g_cursor;
__device__ int   g_esrc[N_EDGES];
__device__ float g_dis[N_NODES];
__device__ __nv_bfloat16 g_xb[(size_t)N_NODES * IN_DIM];    // dis-scaled x
__device__ __nv_bfloat16 g_w1b[(size_t)HID_DIM * IN_DIM];   // [n][k] transposed
__device__ __nv_bfloat16 g_w2b[(size_t)OUT_DIM * HID_DIM];  // [n][k] transposed
__device__ __nv_bfloat16 g_aggxb[(size_t)N_NODES * IN_DIM];
__device__ __nv_bfloat16 g_h1b[(size_t)N_NODES * HID_DIM];
__device__ __nv_bfloat16 g_t2b[(size_t)N_NODES * OUT_DIM];  // dis-scaled t2

// exact bf16 -> f32 unpack (one ALU op each)
__device__ __forceinline__ float bflo(uint32_t u) { return __uint_as_float(u << 16); }
__device__ __forceinline__ float bfhi(uint32_t u) { return __uint_as_float(u & 0xFFFF0000u); }

// ------- hist (atomic-latency-bound) + W conversions (streaming, fused) ----
__global__ void k_hist_w(const int* __restrict__ dst,
                         const float* __restrict__ W1,
                         const float* __restrict__ W2, int e) {
    int i = blockIdx.x * blockDim.x + threadIdx.x;
    if (i < e) atomicAdd(&g_count[dst[i]], 1);
    if (i < IN_DIM * HID_DIM) {        // W1[k][n] -> g_w1b[n][k]
        int k = i / HID_DIM, n = i % HID_DIM;
        g_w1b[(size_t)n * IN_DIM + k] = __float2bfloat16_rn(W1[i]);
    }
    if (i < HID_DIM * OUT_DIM) {       // W2[k][n] -> g_w2b[n][k]
        int k = i / OUT_DIM, n = i % OUT_DIM;
        g_w2b[(size_t)n * HID_DIM + k] = __float2bfloat16_rn(W2[i]);
    }
    if (i == 0) g_cursor = 0;
}

// fused per-chunk scan + atomic base grab; SELF-CLEANS g_count for next run.
__global__ __launch_bounds__(1024) void k_offsets(int n) {
    __shared__ int sh[1024];
    __shared__ int sbase;
    int i = blockIdx.x * 1024 + threadIdx.x;
    int c = (i < n) ? g_count[i] : 0;
    if (i < n) g_count[i] = 0;         // self-clean (each i touched by one thread)
    sh[threadIdx.x] = c;
    __syncthreads();
    for (int o = 1; o < 1024; o <<= 1) {
        int t = 0;
        if (threadIdx.x >= o) t = sh[threadIdx.x - o];
        __syncthreads();
        sh[threadIdx.x] += t;
        __syncthreads();
    }
    if (threadIdx.x == 1023) sbase = atomicAdd(&g_cursor, sh[1023]);
    __syncthreads();
    if (i < n) {
        int off = sbase + sh[threadIdx.x] - c;   // exclusive within chunk
        g_off[i] = off;
        g_cur[i] = off;
        g_dis[i] = rsqrtf((float)(c + 1));       // +1 self-loop
    }
}

// ------- place (atomic-latency-bound) + dis-scaled x->bf16 (fused) ---------
// After this kernel, g_cur[d] == segment end for node d.
// g_xb[row] = g_dis[row] * x[row]  (scale folded into conversion).
__global__ void k_place_x(const int* __restrict__ src, const int* __restrict__ dst,
                          const float* __restrict__ x, int e) {
    int i = blockIdx.x * blockDim.x + threadIdx.x;
    if (i < e) {
        int s = src[i], d = dst[i];
        int pos = atomicAdd(&g_cur[d], 1);
        g_esrc[pos] = s;
    }
    int nthreads = gridDim.x * blockDim.x;
    for (int j = i; j < (N_NODES * IN_DIM) / 4; j += nthreads) {
        float4 v = reinterpret_cast<const float4*>(x)[j];
        float ds = g_dis[j >> 5];            // 32 float4 per row
        __nv_bfloat162 p0 = __floats2bfloat162_rn(v.x * ds, v.y * ds);
        __nv_bfloat162 p1 = __floats2bfloat162_rn(v.z * ds, v.w * ds);
        uint2 u;
        u.x = *reinterpret_cast<uint32_t*>(&p0);
        u.y = *reinterpret_cast<uint32_t*>(&p1);
        reinterpret_cast<uint2*>(g_xb)[j] = u;
    }
}

// ------- layer-1 aggregation: unweighted bf16 sum, warp per node -----------
__global__ __launch_bounds__(256) void k_agg128() {
    int gid = blockIdx.x * blockDim.x + threadIdx.x;
    int node = gid >> 5;
    int lane = gid & 31;
    if (node >= N_NODES) return;
    const uint2* xv = reinterpret_cast<const uint2*>(g_xb);  // 32 uint2 per row
    uint2 u = xv[(size_t)node * 32 + lane];                  // self (scaled)
    float a0 = bflo(u.x), a1 = bfhi(u.x), a2 = bflo(u.y), a3 = bfhi(u.y);
    int p = g_off[node];
    int p1 = g_cur[node];              // segment end (off + count)
    for (; p + 4 <= p1; p += 4) {
        int s0 = g_esrc[p], s1 = g_esrc[p + 1], s2 = g_esrc[p + 2], s3 = g_esrc[p + 3];
        uint2 v0 = xv[(size_t)s0 * 32 + lane];
        uint2 v1 = xv[(size_t)s1 * 32 + lane];
        uint2 v2 = xv[(size_t)s2 * 32 + lane];
        uint2 v3 = xv[(size_t)s3 * 32 + lane];
        a0 += bflo(v0.x); a1 += bfhi(v0.x); a2 += bflo(v0.y); a3 += bfhi(v0.y);
        a0 += bflo(v1.x); a1 += bfhi(v1.x); a2 += bflo(v1.y); a3 += bfhi(v1.y);
        a0 += bflo(v2.x); a1 += bfhi(v2.x); a2 += bflo(v2.y); a3 += bfhi(v2.y);
        a0 += bflo(v3.x); a1 += bfhi(v3.x); a2 += bflo(v3.y); a3 += bfhi(v3.y);
    }
    for (; p < p1; p++) {
        int s0 = g_esrc[p];
        uint2 v0 = xv[(size_t)s0 * 32 + lane];
        a0 += bflo(v0.x); a1 += bfhi(v0.x); a2 += bflo(v0.y); a3 += bfhi(v0.y);
    }
    float dd = g_dis[node];
    __nv_bfloat162 r0 = __floats2bfloat162_rn(a0 * dd, a1 * dd);
    __nv_bfloat162 r1 = __floats2bfloat162_rn(a2 * dd, a3 * dd);
    uint2 w;
    w.x = *reinterpret_cast<uint32_t*>(&r0);
    w.y = *reinterpret_cast<uint32_t*>(&r1);
    reinterpret_cast<uint2*>(g_aggxb)[(size_t)node * 32 + lane] = w;
}

// ---------------- bf16 tensor-core GEMM ------------------------------------
__device__ __forceinline__ void mma_bf16(float c[4], const uint32_t a[4], const uint32_t b[2]) {
    asm volatile(
        "mma.sync.aligned.m16n8k16.row.col.f32.bf16.bf16.f32 "
        "{%0,%1,%2,%3}, {%4,%5,%6,%7}, {%8,%9}, {%0,%1,%2,%3};"
        : "+f"(c[0]), "+f"(c[1]), "+f"(c[2]), "+f"(c[3])
        : "r"(a[0]), "r"(a[1]), "r"(a[2]), "r"(a[3]), "r"(b[0]), "r"(b[1]));
}

template <int LAYER, int N_COLS, int K_DIM, int BN, bool RELU, bool ADD_BIAS, bool SCALE_DIS>
__global__ __launch_bounds__(64 * (BN / 32)) void k_gemm_bf16(
        const float* __restrict__ bias, int M) {
    const __nv_bfloat16* __restrict__ A  = (LAYER == 1) ? g_aggxb : g_h1b;
    const __nv_bfloat16* __restrict__ Wb = (LAYER == 1) ? g_w1b   : g_w2b;
    __nv_bfloat16* __restrict__ C        = (LAYER == 1) ? g_h1b   : g_t2b;

    constexpr int BM = 128, BK = 32;
    constexpr int THREADS = 64 * (BN / 32);
    constexpr int AS = 20;   // uint32 stride: 16 data + 4 pad (conflict-free)

    __shared__ uint32_t As32[BM * AS];
    __shared__ uint32_t Bs32[BN * AS];

    int tid = threadIdx.x;
    int warp = tid >> 5, lane = tid & 31;
    int g = lane >> 2, t = lane & 3;
    int wm = warp & 1;
    int wn = warp >> 1;
    int row0 = blockIdx.x * BM;
    int col0 = blockIdx.y * BN;

    float c[4][4][4];
    #pragma unroll
    for (int i = 0; i < 4; i++)
        #pragma unroll
        for (int j = 0; j < 4; j++)
            #pragma unroll
            for (int r = 0; r < 4; r++) c[i][j][r] = 0.0f;

    for (int k0 = 0; k0 < K_DIM; k0 += BK) {
        constexpr int ALOADS = (BM * 4) / THREADS;
        #pragma unroll
        for (int i = 0; i < ALOADS; i++) {
            int f = tid + i * THREADS;
            int row = f >> 2, q = f & 3;
            int gr = row0 + row;
            uint4 u = make_uint4(0, 0, 0, 0);
            if (gr < M) u = *reinterpret_cast<const uint4*>(A + (size_t)gr * K_DIM + k0 + q * 8);
            uint32_t* p = &As32[row * AS + q * 4];
            p[0] = u.x; p[1] = u.y; p[2] = u.z; p[3] = u.w;
        }
        constexpr int BLOADS = (BN * 4) / THREADS;
        #pragma unroll
        for (int i = 0; i < BLOADS; i++) {
            int f = tid + i * THREADS;
            int row = f >> 2, q = f & 3;
            uint4 u = *reinterpret_cast<const uint4*>(Wb + (size_t)(col0 + row) * K_DIM + k0 + q * 8);
            uint32_t* p = &Bs32[row * AS + q * 4];
            p[0] = u.x; p[1] = u.y; p[2] = u.z; p[3] = u.w;
        }
        __syncthreads();

        #pragma unroll
        for (int ch = 0; ch < 2; ch++) {
            int kb2 = ch * 8;
            uint32_t a[4][4], b[4][2];
            #pragma unroll
            for (int mt = 0; mt < 4; mt++) {
                int r = wm * 64 + mt * 16 + g;
                a[mt][0] = As32[r * AS + kb2 + t];
                a[mt][1] = As32[(r + 8) * AS + kb2 + t];
                a[mt][2] = As32[r * AS + kb2 + 4 + t];
                a[mt][3] = As32[(r + 8) * AS + kb2 + 4 + t];
            }
            #pragma unroll
            for (int nt = 0; nt < 4; nt++) {
                int cc = wn * 32 + nt * 8 + g;
                b[nt][0] = Bs32[cc * AS + kb2 + t];
                b[nt][1] = Bs32[cc * AS + kb2 + 4 + t];
            }
            #pragma unroll
            for (int mt = 0; mt < 4; mt++)
                #pragma unroll
                for (int nt = 0; nt < 4; nt++)
                    mma_bf16(c[mt][nt], a[mt], b[nt]);
        }
        __syncthreads();
    }

    #pragma unroll
    for (int mt = 0; mt < 4; mt++) {
        int r0 = row0 + wm * 64 + mt * 16 + g;
        float sc0 = 1.0f, sc8 = 1.0f;
        if (SCALE_DIS) {
            if (r0 < M) sc0 = g_dis[r0];
            if (r0 + 8 < M) sc8 = g_dis[r0 + 8];
        }
        #pragma unroll
        for (int nt = 0; nt < 4; nt++) {
            int col = col0 + wn * 32 + nt * 8 + 2 * t;
            float bb0 = 0.f, bb1 = 0.f;
            if (ADD_BIAS) { bb0 = bias[col]; bb1 = bias[col + 1]; }
            if (r0 < M) {
                float v0 = c[mt][nt][0] + bb0;
                float v1 = c[mt][nt][1] + bb1;
                if (RELU) { v0 = fmaxf(v0, 0.f); v1 = fmaxf(v1, 0.f); }
                if (SCALE_DIS) { v0 *= sc0; v1 *= sc0; }
                *reinterpret_cast<__nv_bfloat162*>(C + (size_t)r0 * N_COLS + col) =
                    __floats2bfloat162_rn(v0, v1);
            }
            if (r0 + 8 < M) {
                float v0 = c[mt][nt][2] + bb0;
                float v1 = c[mt][nt][3] + bb1;
                if (RELU) { v0 = fmaxf(v0, 0.f); v1 = fmaxf(v1, 0.f); }
                if (SCALE_DIS) { v0 *= sc8; v1 *= sc8; }
                *reinterpret_cast<__nv_bfloat162*>(C + (size_t)(r0 + 8) * N_COLS + col) =
                    __floats2bfloat162_rn(v0, v1);
            }
        }
    }
}

// ------- layer-2 aggregation (unweighted sum) + bias + log_softmax ---------
__global__ __launch_bounds__(256) void k_agg64_softmax(float* __restrict__ out,
                                                       const float* __restrict__ b2,
                                                       const float* __restrict__ x,
                                                       const float* __restrict__ W1) {
    int gid = blockIdx.x * blockDim.x + threadIdx.x;
    int node = gid >> 5;
    int lane = gid & 31;
    if (node >= N_NODES) return;
    const uint32_t* tv = reinterpret_cast<const uint32_t*>(g_t2b);  // 32 bf162 per row
    uint32_t u = tv[(size_t)node * 32 + lane];                      // self (scaled)
    float ax = bflo(u), ay = bfhi(u);
    int p = g_off[node];
    int p1 = g_cur[node];              // segment end
    for (; p + 4 <= p1; p += 4) {
        int s0 = g_esrc[p], s1 = g_esrc[p + 1], s2 = g_esrc[p + 2], s3 = g_esrc[p + 3];
        uint32_t v0 = tv[(size_t)s0 * 32 + lane];
        uint32_t v1 = tv[(size_t)s1 * 32 + lane];
        uint32_t v2 = tv[(size_t)s2 * 32 + lane];
        uint32_t v3 = tv[(size_t)s3 * 32 + lane];
        ax += bflo(v0); ay += bfhi(v0);
        ax += bflo(v1); ay += bfhi(v1);
        ax += bflo(v2); ay += bfhi(v2);
        ax += bflo(v3); ay += bfhi(v3);
    }
    for (; p < p1; p++) {
        uint32_t v0 = tv[(size_t)g_esrc[p] * 32 + lane];
        ax += bflo(v0); ay += bfhi(v0);
    }
    float dd = g_dis[node];

    // --- diagnostic canaries (0.0 contribution when all stages are live) ---
    float canary = 0.0f;
    if (x[5] == 0.0f && x[777] == 0.0f)                       canary += 0.64f;
    if (W1[3] == 0.0f && W1[1000] == 0.0f)                    canary += 0.32f;
    if (__bfloat162float(g_xb[12345]) == 0.0f &&
        __bfloat162float(g_xb[6399999]) == 0.0f)              canary += 0.16f;
    if (__bfloat162float(g_h1b[54321]) == 0.0f &&
        __bfloat162float(g_h1b[9000001]) == 0.0f)             canary += 0.08f;
    if (g_dis[7] == 0.0f)                                     canary += 0.04f;
    if (g_cursor != N_EDGES)                                  canary += 0.02f;

    float2 bb = reinterpret_cast<const float2*>(b2)[lane];
    float vx = ax * dd + bb.x + canary;
    float vy = ay * dd + bb.y - canary;

    float m = fmaxf(vx, vy);
    #pragma unroll
    for (int o = 16; o > 0; o >>= 1) m = fmaxf(m, __shfl_xor_sync(0xFFFFFFFF, m, o));
    float s = expf(vx - m) + expf(vy - m);
    #pragma unroll
    for (int o = 16; o > 0; o >>= 1) s += __shfl_xor_sync(0xFFFFFFFF, s, o);
    float lse = m + logf(s);

    float2 r;
    r.x = vx - lse;
    r.y = vy - lse;
    reinterpret_cast<float2*>(out + (size_t)node * OUT_DIM)[lane] = r;
}

// ---------------------------------------------------------------------------
extern "C" void kernel_launch(void* const* d_in, const int* in_sizes, int n_in,
                              void* d_out, int out_size) {
    const float* x  = nullptr;   // 6400000
    const int*   ei = nullptr;   // 1600000
    const float* W1 = nullptr;   // 32768
    const float* b1 = nullptr;   // 256
    const float* W2 = nullptr;   // 16384
    const float* b2 = nullptr;   // 64
    for (int i = 0; i < n_in; i++) {
        switch (in_sizes[i]) {
            case N_NODES * IN_DIM:   x  = (const float*)d_in[i]; break;
            case 2 * N_EDGES:        ei = (const int*)d_in[i];   break;
            case IN_DIM * HID_DIM:   W1 = (const float*)d_in[i]; break;
            case HID_DIM:            b1 = (const float*)d_in[i]; break;
            case HID_DIM * OUT_DIM:  W2 = (const float*)d_in[i]; break;
            case OUT_DIM:            b2 = (const float*)d_in[i]; break;
            default: break;
        }
    }
    float* out = (float*)d_out;

    const int N = N_NODES;
    const int E = N_EDGES;
    const int* src = ei;
    const int* dst = ei + E;

    const int T = 256;

    // CSR build; g_count arrives zeroed (loader on first call, k_offsets after)
    k_hist_w<<<(E + T - 1) / T, T>>>(dst, W1, W2, E);
    k_offsets<<<(N + 1023) / 1024, 1024>>>(N);
    k_place_x<<<(E + T - 1) / T, T>>>(src, dst, x, E);

    // layer 1: unweighted gather-sum (dim 128), bf16 GEMM 128->256 (+bias+relu)
    k_agg128<<<(N * 32 + T - 1) / T, T>>>();
    {
        dim3 g((N + 127) / 128, HID_DIM / 128);   // (391, 2)
        k_gemm_bf16<1, HID_DIM, IN_DIM, 128, true, true, false><<<g, 256>>>(b1, N);
    }
    // layer 2: bf16 GEMM 256->64 (epilogue scales by dis), gather-sum + softmax
    {
        dim3 g((N + 127) / 128, 1);               // (391, 1)
        k_gemm_bf16<2, OUT_DIM, HID_DIM, 64, false, false, true><<<g, 128>>>(nullptr, N);
    }
    k_agg64_softmax<<<(N * 32 + T - 1) / T, T>>>(out, b2, x, W1);
}